// round 13
// baseline (speedup 1.0000x reference)
#include <cuda_runtime.h>
#include <cuda_bf16.h>
#include <math.h>
#include <stdint.h>

#define E_EDGES 65536
#define N_NODES 4096

// ---------------- device scratch ----------------
__device__ float g_w3j[678];
__device__ float g_shc[2];
__device__ float g_w[E_EDGES * 64];
__device__ float g_Y[E_EDGES * 16];
__device__ float g_len[E_EDGES];
__device__ int   g_cnt[N_NODES];
__device__ int   g_off[N_NODES + 1];
__device__ int   g_cursor[N_NODES];
__device__ int   g_sorted[E_EDGES];
__device__ float g_nodewY[N_NODES * 1024];
__device__ float g_S[E_EDGES * 192];
// bf16 hi/lo planes of the GEMM A matrices (row-major, K=320)
__device__ unsigned short g_A1h[E_EDGES * 3 * 320];
__device__ unsigned short g_A1l[E_EDGES * 3 * 320];
__device__ unsigned short g_A2h[E_EDGES * 5 * 320];
__device__ unsigned short g_A2l[E_EDGES * 5 * 320];

// ---------- f32x2 helpers ----------
__device__ __forceinline__ unsigned long long pack2(float x) {
    unsigned long long r;
    unsigned int xi = __float_as_uint(x);
    asm("mov.b64 %0, {%1, %1};" : "=l"(r) : "r"(xi));
    return r;
}
__device__ __forceinline__ float2 unpack2(unsigned long long v) {
    unsigned int lo, hi;
    asm("mov.b64 {%0, %1}, %2;" : "=r"(lo), "=r"(hi) : "l"(v));
    return make_float2(__uint_as_float(lo), __uint_as_float(hi));
}
#define FMA2(acc, a, b) \
    asm("fma.rn.f32x2 %0, %1, %2, %0;" : "+l"(acc) : "l"(a), "l"(b))

// ---------- bf16 helpers ----------
__device__ __forceinline__ unsigned short f2bf(float v) {
    __nv_bfloat16 b = __float2bfloat16(v);
    return *reinterpret_cast<unsigned short*>(&b);
}
__device__ __forceinline__ float bf2f(unsigned short s) {
    __nv_bfloat16 b = *reinterpret_cast<__nv_bfloat16*>(&s);
    return __bfloat162float(b);
}

// ---------- classic tensor-core mma (base ISA, works on sm_103) ----------
__device__ __forceinline__ void mma16816(float* c, const uint32_t* a, uint32_t b0, uint32_t b1) {
    asm volatile(
        "mma.sync.aligned.m16n8k16.row.col.f32.bf16.bf16.f32 "
        "{%0,%1,%2,%3}, {%4,%5,%6,%7}, {%8,%9}, {%0,%1,%2,%3};"
        : "+f"(c[0]), "+f"(c[1]), "+f"(c[2]), "+f"(c[3])
        : "r"(a[0]), "r"(a[1]), "r"(a[2]), "r"(a[3]), "r"(b0), "r"(b1));
}

__device__ double dfact(int n) {
    double r = 1.0;
    for (int i = 2; i <= n; ++i) r *= (double)i;
    return r;
}

__device__ double su2_cg(int j1, int j2, int j3, int m1, int m2, int m3) {
    if (m3 != m1 + m2) return 0.0;
    double pref = sqrt((2.0 * j3 + 1.0) * dfact(j3 + j1 - j2) * dfact(j3 - j1 + j2) *
                       dfact(j1 + j2 - j3) / dfact(j1 + j2 + j3 + 1));
    pref *= sqrt(dfact(j3 + m3) * dfact(j3 - m3) * dfact(j1 - m1) * dfact(j1 + m1) *
                 dfact(j2 - m2) * dfact(j2 + m2));
    double s = 0.0;
    for (int k = 0; k <= j1 + j2 - j3; ++k) {
        int d0 = k, d1 = j1 + j2 - j3 - k, d2 = j1 - m1 - k, d3 = j2 + m2 - k;
        int d4 = j3 - j2 + m1 + k, d5 = j3 - j1 - m2 + k;
        if (d0 < 0 || d1 < 0 || d2 < 0 || d3 < 0 || d4 < 0 || d5 < 0) continue;
        double den = dfact(d0) * dfact(d1) * dfact(d2) * dfact(d3) * dfact(d4) * dfact(d5);
        s += ((k & 1) ? -1.0 : 1.0) / den;
    }
    return pref * s;
}

__device__ void build_q(int l, double* qr, double* qi) {
    for (int i = 0; i < 49; ++i) { qr[i] = 0.0; qi[i] = 0.0; }
    const double is2 = 0.70710678118654752440;
    for (int m = -l; m < 0; ++m) {
        qr[(l + m) * 7 + (l - m)] = is2;
        qi[(l + m) * 7 + (l + m)] = -is2;
    }
    qr[l * 7 + l] = 1.0;
    for (int m = 1; m <= l; ++m) {
        double sg = (m & 1) ? -1.0 : 1.0;
        qr[(l + m) * 7 + (l + m)] = sg * is2;
        qi[(l + m) * 7 + (l - m)] = sg * is2;
    }
    int lm = l & 3;
    double pr, pi;
    if (lm == 0) { pr = 1; pi = 0; }
    else if (lm == 1) { pr = 0; pi = -1; }
    else if (lm == 2) { pr = -1; pi = 0; }
    else { pr = 0; pi = 1; }
    for (int i = 0; i < 49; ++i) {
        double r = qr[i], im = qi[i];
        qr[i] = pr * r - pi * im;
        qi[i] = pr * im + pi * r;
    }
}

__global__ void w3j_kernel() {
    const int L1[14] = {0, 1, 2, 0, 1, 1, 2, 3, 0, 1, 2, 2, 3, 2};
    const int L2[14] = {0, 1, 2, 1, 0, 2, 1, 2, 2, 1, 0, 2, 1, 1};
    const int L3[14] = {0, 0, 0, 1, 1, 1, 1, 1, 2, 2, 2, 2, 2, 3};
    const int OFFS[14] = {0, 1, 10, 35, 44, 53, 98, 143, 248, 273, 318, 343, 468, 573};
    int p = blockIdx.x;
    int t = threadIdx.x;
    int l1 = L1[p], l2 = L2[p], l3 = L3[p];
    int n1 = 2 * l1 + 1, n2 = 2 * l2 + 1, n3 = 2 * l3 + 1;
    int ntot = n1 * n2 * n3;

    __shared__ double sC[125];
    __shared__ double q1r[49], q1i[49], q2r[49], q2i[49], q3r[49], q3i[49];
    __shared__ double red[128];

    if (t < ntot) {
        int a = t / (n2 * n3);
        int b = (t / n3) % n2;
        int c = t % n3;
        sC[t] = su2_cg(l1, l2, l3, a - l1, b - l2, c - l3);
    }
    if (t == 0) {
        build_q(l1, q1r, q1i);
        build_q(l2, q2r, q2i);
        build_q(l3, q3r, q3i);
    }
    __syncthreads();

    double cr = 0.0;
    if (t < ntot) {
        int i = t / (n2 * n3);
        int j = (t / n3) % n2;
        int k = t % n3;
        for (int a = 0; a < n1; ++a) {
            double ar = q1r[a * 7 + i], ai = q1i[a * 7 + i];
            for (int b = 0; b < n2; ++b) {
                double br = q2r[b * 7 + j], bi = q2i[b * 7 + j];
                double tr = ar * br - ai * bi;
                double ti = ar * bi + ai * br;
                for (int c = 0; c < n3; ++c) {
                    double c3r = q3r[c * 7 + k], c3i = q3i[c * 7 + k];
                    double re = tr * c3r + ti * c3i;
                    cr += re * sC[(a * n2 + b) * n3 + c];
                }
            }
        }
    }
    red[t] = (t < ntot) ? cr * cr : 0.0;
    __syncthreads();
    for (int s = 64; s > 0; s >>= 1) {
        if (t < s) red[t] += red[t + s];
        __syncthreads();
    }
    double inv = 1.0 / sqrt(red[0]);
    if (t < ntot) g_w3j[OFFS[p] + t] = (float)(cr * inv);
}

__global__ void shc_kernel() {
    double u0[3] = {0.3, -0.4, sqrt(0.75)};
    double y1[3];
    for (int i = 0; i < 3; ++i) y1[i] = sqrt(3.0) * u0[i];
    double y2r[5] = {0, 0, 0, 0, 0};
    for (int i = 0; i < 3; ++i)
        for (int j = 0; j < 3; ++j)
            for (int k = 0; k < 5; ++k)
                y2r[k] += y1[i] * y1[j] * (double)g_w3j[273 + (i * 3 + j) * 5 + k];
    double n2s = 0;
    for (int k = 0; k < 5; ++k) n2s += y2r[k] * y2r[k];
    double c2 = sqrt(5.0) / sqrt(n2s);
    double y3r[7] = {0, 0, 0, 0, 0, 0, 0};
    for (int i = 0; i < 5; ++i)
        for (int j = 0; j < 3; ++j)
            for (int k = 0; k < 7; ++k)
                y3r[k] += (c2 * y2r[i]) * y1[j] * (double)g_w3j[573 + (i * 3 + j) * 7 + k];
    double n3s = 0;
    for (int k = 0; k < 7; ++k) n3s += y3r[k] * y3r[k];
    double c3 = sqrt(7.0) / sqrt(n3s);
    g_shc[0] = (float)c2;
    g_shc[1] = (float)c3;
}

__global__ void zero_cnt_kernel() {
    int i = blockIdx.x * blockDim.x + threadIdx.x;
    if (i < N_NODES) g_cnt[i] = 0;
}

// ------------- edge pre -------------
__global__ __launch_bounds__(256) void edge_pre_kernel(
    const float* __restrict__ vectors, const float* __restrict__ x,
    const float* __restrict__ Ww, const int* __restrict__ senders) {
    __shared__ float sWwT[4096];
    __shared__ float shx[1024];
    int t = threadIdx.x;
    int slot = t >> 6, u = t & 63;
    for (int i = t; i < 4096; i += 256) {
        int f4 = i >> 8, uu = (i >> 2) & 63, fr = i & 3;
        sWwT[i] = Ww[(f4 * 4 + fr) * 64 + uu];
    }
    __syncthreads();

    for (int it = 0; it < 16; ++it) {
        int e = blockIdx.x * 64 + it * 4 + slot;
        shx[slot * 256 + u] = x[e * 64 + u];
        __syncthreads();
        unsigned long long acc01 = 0ull, acc23 = 0ull;
        const ulonglong2* xp = (const ulonglong2*)(shx + slot * 256);
#pragma unroll
        for (int f4 = 0; f4 < 16; ++f4) {
            ulonglong2 xv = xp[f4];
            ulonglong2 wv = *(const ulonglong2*)(sWwT + f4 * 256 + u * 4);
            FMA2(acc01, xv.x, wv.x);
            FMA2(acc23, xv.y, wv.y);
        }
        float2 p01 = unpack2(acc01);
        float2 p23 = unpack2(acc23);
        float acc = (p01.x + p01.y) + (p23.x + p23.y);
        g_w[e * 64 + u] = acc * 0.125f;

        if (u < 16) {
            float vx = vectors[e * 3 + 0], vy = vectors[e * 3 + 1], vz = vectors[e * 3 + 2];
            float len = sqrtf(vx * vx + vy * vy + vz * vz);
            float inv = 1.0f / (len + 1e-12f);
            float y1[3] = {1.7320508075688772f * vx * inv,
                           1.7320508075688772f * vy * inv,
                           1.7320508075688772f * vz * inv};
            float C2 = g_shc[0], C3 = g_shc[1];
            float y2[5] = {0, 0, 0, 0, 0};
#pragma unroll
            for (int i = 0; i < 3; ++i)
#pragma unroll
                for (int j = 0; j < 3; ++j) {
                    float ab = y1[i] * y1[j];
#pragma unroll
                    for (int k = 0; k < 5; ++k) y2[k] += ab * g_w3j[273 + (i * 3 + j) * 5 + k];
                }
#pragma unroll
            for (int k = 0; k < 5; ++k) y2[k] *= C2;
            float Yv;
            if (u == 0) Yv = 1.0f;
            else if (u < 4) Yv = y1[u - 1];
            else if (u < 9) Yv = y2[u - 4];
            else {
                int k = u - 9;
                float s = 0.f;
#pragma unroll
                for (int i = 0; i < 5; ++i)
#pragma unroll
                    for (int j = 0; j < 3; ++j)
                        s += y2[i] * y1[j] * g_w3j[573 + (i * 3 + j) * 7 + k];
                Yv = C3 * s;
            }
            g_Y[e * 16 + u] = Yv;
            if (u == 0) {
                g_len[e] = len;
                atomicAdd(&g_cnt[senders[e]], 1);
            }
        }
        __syncthreads();
    }
}

// ------------- scan -------------
__global__ void scan_kernel() {
    int t = threadIdx.x;
    int b = t * 4;
    int v0 = g_cnt[b], v1 = g_cnt[b + 1], v2 = g_cnt[b + 2], v3 = g_cnt[b + 3];
    int tsum = v0 + v1 + v2 + v3;
    int xv = tsum;
#pragma unroll
    for (int o = 1; o < 32; o <<= 1) {
        int y = __shfl_up_sync(0xffffffffu, xv, o);
        if ((t & 31) >= o) xv += y;
    }
    __shared__ int wsum[32];
    if ((t & 31) == 31) wsum[t >> 5] = xv;
    __syncthreads();
    if (t < 32) {
        int z = wsum[t];
#pragma unroll
        for (int o = 1; o < 32; o <<= 1) {
            int y = __shfl_up_sync(0xffffffffu, z, o);
            if (t >= o) z += y;
        }
        wsum[t] = z;
    }
    __syncthreads();
    int excl = xv - tsum + ((t >= 32) ? wsum[(t >> 5) - 1] : 0);
    int run = excl;
    g_off[b] = run; g_cursor[b] = run; run += v0;
    g_off[b + 1] = run; g_cursor[b + 1] = run; run += v1;
    g_off[b + 2] = run; g_cursor[b + 2] = run; run += v2;
    g_off[b + 3] = run; g_cursor[b + 3] = run; run += v3;
    if (t == 1023) g_off[N_NODES] = run;
}

__global__ void scatter_kernel(const int* __restrict__ senders) {
    int e = blockIdx.x * blockDim.x + threadIdx.x;
    int pos = atomicAdd(&g_cursor[senders[e]], 1);
    g_sorted[pos] = e;
}

// ------------- node accumulate -------------
__global__ __launch_bounds__(256) void node_accum_kernel() {
    int n = blockIdx.x, t = threadIdx.x;
    int s = g_off[n];
    int cnt = g_off[n + 1] - s;
    int uu = t >> 4, ii = t & 15;
    __shared__ float sw[64];
    __shared__ float sy[16];
    float a0 = 0, a1 = 0, a2 = 0, a3 = 0;
    for (int q = 0; q < cnt; ++q) {
        int e = g_sorted[s + q];
        __syncthreads();
        if (t < 64) sw[t] = g_w[e * 64 + t];
        else if (t < 80) sy[t - 64] = g_Y[e * 16 + (t - 64)];
        __syncthreads();
        float yv = sy[ii];
        a0 += sw[uu] * yv;
        a1 += sw[uu + 16] * yv;
        a2 += sw[uu + 32] * yv;
        a3 += sw[uu + 48] * yv;
    }
    float* dst = &g_nodewY[n * 1024];
    dst[uu * 16 + ii] = 0.25f * a0;
    dst[(uu + 16) * 16 + ii] = 0.25f * a1;
    dst[(uu + 32) * 16 + ii] = 0.25f * a2;
    dst[(uu + 48) * 16 + ii] = 0.25f * a3;
}

// ------------- main edge kernel: TP paths -> S, bf16 hi/lo A planes -------------
__global__ __launch_bounds__(256) void edge_main_kernel(
    const float* __restrict__ V, const int* __restrict__ senders) {
    __shared__ float sw3j[678];
    int t = threadIdx.x;
    for (int i = t; i < 678; i += 256) sw3j[i] = g_w3j[i];
    int slot = t >> 6, u = t & 63;
    int e = blockIdx.x * 4 + slot;
    int n = senders[e];
    __syncthreads();

    float wy[16];
    {
        const float4* wp = (const float4*)&g_nodewY[n * 1024 + u * 16];
        float4 q0 = wp[0], q1 = wp[1], q2 = wp[2], q3 = wp[3];
        wy[0] = q0.x; wy[1] = q0.y; wy[2] = q0.z; wy[3] = q0.w;
        wy[4] = q1.x; wy[5] = q1.y; wy[6] = q1.z; wy[7] = q1.w;
        wy[8] = q2.x; wy[9] = q2.y; wy[10] = q2.z; wy[11] = q2.w;
        wy[12] = q3.x; wy[13] = q3.y; wy[14] = q3.z; wy[15] = q3.w;
    }
    const float* Vr = V + (size_t)e * 576;
    float v0 = Vr[u];
    float v1[3], v2[5];
#pragma unroll
    for (int j = 0; j < 3; ++j) v1[j] = Vr[64 + u * 3 + j];
#pragma unroll
    for (int j = 0; j < 5; ++j) v2[j] = Vr[256 + u * 5 + j];

    // scalar paths
    float s0 = wy[0] * v0 * sw3j[0];
    float s1 = 0.f;
#pragma unroll
    for (int i = 0; i < 3; ++i)
#pragma unroll
        for (int j = 0; j < 3; ++j) s1 += wy[1 + i] * v1[j] * sw3j[1 + i * 3 + j];
    float s2 = 0.f;
#pragma unroll
    for (int i = 0; i < 5; ++i)
#pragma unroll
        for (int j = 0; j < 5; ++j) s2 += wy[4 + i] * v2[j] * sw3j[10 + i * 5 + j];
    g_S[e * 192 + u] = s0;
    g_S[e * 192 + 64 + u] = s1;
    g_S[e * 192 + 128 + u] = s2;

    // l3=1 paths
    float p[5][3];
#pragma unroll
    for (int pa = 0; pa < 5; ++pa)
#pragma unroll
        for (int k = 0; k < 3; ++k) p[pa][k] = 0.f;
#pragma unroll
    for (int j = 0; j < 3; ++j) {
        float ab = wy[0] * v1[j];
#pragma unroll
        for (int k = 0; k < 3; ++k) p[0][k] += ab * sw3j[35 + j * 3 + k];
    }
#pragma unroll
    for (int i = 0; i < 3; ++i) {
        float ab = wy[1 + i] * v0;
#pragma unroll
        for (int k = 0; k < 3; ++k) p[1][k] += ab * sw3j[44 + i * 3 + k];
    }
#pragma unroll
    for (int i = 0; i < 3; ++i)
#pragma unroll
        for (int j = 0; j < 5; ++j) {
            float ab = wy[1 + i] * v2[j];
#pragma unroll
            for (int k = 0; k < 3; ++k) p[2][k] += ab * sw3j[53 + (i * 5 + j) * 3 + k];
        }
#pragma unroll
    for (int i = 0; i < 5; ++i)
#pragma unroll
        for (int j = 0; j < 3; ++j) {
            float ab = wy[4 + i] * v1[j];
#pragma unroll
            for (int k = 0; k < 3; ++k) p[3][k] += ab * sw3j[98 + (i * 3 + j) * 3 + k];
        }
#pragma unroll
    for (int i = 0; i < 7; ++i)
#pragma unroll
        for (int j = 0; j < 5; ++j) {
            float ab = wy[9 + i] * v2[j];
#pragma unroll
            for (int k = 0; k < 3; ++k) p[4][k] += ab * sw3j[143 + (i * 5 + j) * 3 + k];
        }

    // l3=2 paths
    float dd[5][5];
#pragma unroll
    for (int pa = 0; pa < 5; ++pa)
#pragma unroll
        for (int k = 0; k < 5; ++k) dd[pa][k] = 0.f;
#pragma unroll
    for (int j = 0; j < 5; ++j) {
        float ab = wy[0] * v2[j];
#pragma unroll
        for (int k = 0; k < 5; ++k) dd[0][k] += ab * sw3j[248 + j * 5 + k];
    }
#pragma unroll
    for (int i = 0; i < 3; ++i)
#pragma unroll
        for (int j = 0; j < 3; ++j) {
            float ab = wy[1 + i] * v1[j];
#pragma unroll
            for (int k = 0; k < 5; ++k) dd[1][k] += ab * sw3j[273 + (i * 3 + j) * 5 + k];
        }
#pragma unroll
    for (int i = 0; i < 5; ++i) {
        float ab = wy[4 + i] * v0;
#pragma unroll
        for (int k = 0; k < 5; ++k) dd[2][k] += ab * sw3j[318 + i * 5 + k];
    }
#pragma unroll
    for (int i = 0; i < 5; ++i)
#pragma unroll
        for (int j = 0; j < 5; ++j) {
            float ab = wy[4 + i] * v2[j];
#pragma unroll
            for (int k = 0; k < 5; ++k) dd[3][k] += ab * sw3j[343 + (i * 5 + j) * 5 + k];
        }
#pragma unroll
    for (int i = 0; i < 7; ++i)
#pragma unroll
        for (int j = 0; j < 3; ++j) {
            float ab = wy[9 + i] * v1[j];
#pragma unroll
            for (int k = 0; k < 5; ++k) dd[4][k] += ab * sw3j[468 + (i * 3 + j) * 5 + k];
        }

    const float SQ3 = 1.7320508075688772f;
    const float SQ5 = 2.2360679774997896f;
#pragma unroll
    for (int k = 0; k < 3; ++k) {
        size_t rb = ((size_t)e * 3 + k) * 320;
#pragma unroll
        for (int pa = 0; pa < 5; ++pa) {
            float val = SQ3 * p[pa][k];
            unsigned short h = f2bf(val);
            g_A1h[rb + pa * 64 + u] = h;
            g_A1l[rb + pa * 64 + u] = f2bf(val - bf2f(h));
        }
    }
#pragma unroll
    for (int k = 0; k < 5; ++k) {
        size_t rb = ((size_t)e * 5 + k) * 320;
#pragma unroll
        for (int pa = 0; pa < 5; ++pa) {
            float val = SQ5 * dd[pa][k];
            unsigned short h = f2bf(val);
            g_A2h[rb + pa * 64 + u] = h;
            g_A2l[rb + pa * 64 + u] = f2bf(val - bf2f(h));
        }
    }
}

// ------------- fused 3-layer MLP + envelope -> out[:, 0:64] (f32x2) -------------
__global__ __launch_bounds__(256) void mlp_kernel(
    const float* __restrict__ x, const float* __restrict__ W1,
    const float* __restrict__ W2, const float* __restrict__ W3,
    float* __restrict__ out) {
    extern __shared__ float smemf[];
    float* sW1T = smemf;
    float* sW2T = smemf + 16384;
    float* sW3T = smemf + 20480;
    float* shh = smemf + 24576;
    float* sh1 = smemf + 25600;
    float* sh2 = smemf + 25856;
    int t = threadIdx.x;
    for (int i = t; i < 16384; i += 256) {
        int f4 = i >> 8, uu = (i >> 2) & 63, fr = i & 3;
        sW1T[i] = W1[(f4 * 4 + fr) * 64 + uu];
    }
    for (int i = t; i < 4096; i += 256) {
        int f4 = i >> 8, uu = (i >> 2) & 63, fr = i & 3;
        sW2T[i] = W2[(f4 * 4 + fr) * 64 + uu];
        sW3T[i] = W3[(f4 * 4 + fr) * 64 + uu];
    }
    __syncthreads();

    int s = t >> 6, u = t & 63;
    for (int it = 0; it < 32; ++it) {
        int ebase = blockIdx.x * 128 + it * 4;
        for (int l = 0; l < 4; ++l) {
            int f = t + l * 256;
            int es = ebase + (f >> 8);
            int idx = f & 255;
            shh[f] = (idx < 64) ? x[es * 64 + idx] : g_S[es * 192 + idx - 64];
        }
        __syncthreads();
        int e = ebase + s;
        unsigned long long a01 = 0ull, a23 = 0ull;
        const ulonglong2* xp = (const ulonglong2*)(shh + s * 256);
#pragma unroll
        for (int f4 = 0; f4 < 64; ++f4) {
            ulonglong2 xv = xp[f4];
            ulonglong2 wv = *(const ulonglong2*)(sW1T + f4 * 256 + u * 4);
            FMA2(a01, xv.x, wv.x);
            FMA2(a23, xv.y, wv.y);
        }
        float2 p01 = unpack2(a01), p23 = unpack2(a23);
        float a1 = ((p01.x + p01.y) + (p23.x + p23.y)) * 0.0625f;
        float h1 = a1 / (1.f + expf(-a1));
        sh1[s * 64 + u] = h1;
        __syncthreads();
        a01 = 0ull; a23 = 0ull;
        const ulonglong2* hp = (const ulonglong2*)(sh1 + s * 64);
#pragma unroll
        for (int f4 = 0; f4 < 16; ++f4) {
            ulonglong2 xv = hp[f4];
            ulonglong2 wv = *(const ulonglong2*)(sW2T + f4 * 256 + u * 4);
            FMA2(a01, xv.x, wv.x);
            FMA2(a23, xv.y, wv.y);
        }
        p01 = unpack2(a01); p23 = unpack2(a23);
        float a2 = ((p01.x + p01.y) + (p23.x + p23.y)) * 0.125f;
        float h2 = a2 / (1.f + expf(-a2));
        sh2[s * 64 + u] = h2;
        __syncthreads();
        a01 = 0ull; a23 = 0ull;
        const ulonglong2* hp2 = (const ulonglong2*)(sh2 + s * 64);
#pragma unroll
        for (int f4 = 0; f4 < 16; ++f4) {
            ulonglong2 xv = hp2[f4];
            ulonglong2 wv = *(const ulonglong2*)(sW3T + f4 * 256 + u * 4);
            FMA2(a01, xv.x, wv.x);
            FMA2(a23, xv.y, wv.y);
        }
        p01 = unpack2(a01); p23 = unpack2(a23);
        float a3 = ((p01.x + p01.y) + (p23.x + p23.y)) * 0.125f;
        float d = g_len[e];
        float d3 = d * d * d;
        float d6 = d3 * d3, d7 = d6 * d, d8 = d7 * d;
        float env = (d < 1.0f) ? (1.0f - 28.0f * d6 + 48.0f * d7 - 21.0f * d8) : 0.0f;
        out[(size_t)e * 576 + u] = env * a3;
        __syncthreads();
    }
}

// ------------- mma.sync bf16-split GEMM -------------
// Block: 8 warps, 128 rows; warp w -> rows [w*16, w*16+16). N=64 (8 n8-tiles).
// B (Wl) hi/lo in smem col-major [n][k], stride 328 bf16 (conflict-free).
// A fragments loaded directly from global bf16 planes.
// blocks [0,1536): A1 (mode 0); [1536,4096): A2 (mode 1).
#define BSTR 328
#define GM_SMEM (2 * 64 * BSTR * 2)   // 83968 bytes

__global__ __launch_bounds__(256) void gemm_mma_kernel(
    const float* __restrict__ Wl1, const float* __restrict__ Wl2,
    float* __restrict__ out) {
    extern __shared__ unsigned short sB[];
    unsigned short* sBh = sB;
    unsigned short* sBl = sB + 64 * BSTR;

    int t = threadIdx.x;
    int w = t >> 5, lane = t & 31;
    int gid = lane >> 2, tid = lane & 3;

    int mode, row0;
    const float* Wl;
    const unsigned short *Ah, *Al;
    if (blockIdx.x < 1536) {
        mode = 0; row0 = blockIdx.x * 128;
        Wl = Wl1; Ah = g_A1h; Al = g_A1l;
    } else {
        mode = 1; row0 = (blockIdx.x - 1536) * 128;
        Wl = Wl2; Ah = g_A2h; Al = g_A2l;
    }

    // Fill B smem: col-major [n][k], hi/lo split. Wl is [v=320][n=64] row-major.
    for (int i = t; i < 320 * 64; i += 256) {
        int v = i >> 6, n = i & 63;
        float f = Wl[i];
        unsigned short h = f2bf(f);
        sBh[n * BSTR + v] = h;
        sBl[n * BSTR + v] = f2bf(f - bf2f(h));
    }
    __syncthreads();

    // accumulators: 8 n-tiles x 4 f32
    float c[8][4];
#pragma unroll
    for (int nt = 0; nt < 8; ++nt)
#pragma unroll
        for (int j = 0; j < 4; ++j) c[nt][j] = 0.f;

    int r0 = row0 + w * 16 + gid;      // row for a0/a2 (c0,c1)
    const unsigned short* ahp = Ah + (size_t)r0 * 320 + tid * 2;
    const unsigned short* alp = Al + (size_t)r0 * 320 + tid * 2;

    for (int kc = 0; kc < 20; ++kc) {
        int ko = kc * 16;
        uint32_t ah[4], al[4];
        ah[0] = *(const uint32_t*)(ahp + ko);
        ah[1] = *(const uint32_t*)(ahp + 8 * 320 + ko);
        ah[2] = *(const uint32_t*)(ahp + ko + 8);
        ah[3] = *(const uint32_t*)(ahp + 8 * 320 + ko + 8);
        al[0] = *(const uint32_t*)(alp + ko);
        al[1] = *(const uint32_t*)(alp + 8 * 320 + ko);
        al[2] = *(const uint32_t*)(alp + ko + 8);
        al[3] = *(const uint32_t*)(alp + 8 * 320 + ko + 8);
#pragma unroll
        for (int nt = 0; nt < 8; ++nt) {
            const unsigned short* bh = sBh + (nt * 8 + gid) * BSTR + ko + tid * 2;
            const unsigned short* bl = sBl + (nt * 8 + gid) * BSTR + ko + tid * 2;
            uint32_t bh0 = *(const uint32_t*)(bh);
            uint32_t bh1 = *(const uint32_t*)(bh + 8);
            uint32_t bl0 = *(const uint32_t*)(bl);
            uint32_t bl1 = *(const uint32_t*)(bl + 8);
            mma16816(c[nt], ah, bh0, bh1);
            mma16816(c[nt], ah, bl0, bl1);
            mma16816(c[nt], al, bh0, bh1);
        }
    }

    const float alpha = 0.05590169943749474f;  // 1/sqrt(320)
    // D layout: c0 = D[gid][tid*2], c1 = D[gid][tid*2+1],
    //           c2 = D[gid+8][tid*2], c3 = D[gid+8][tid*2+1]
#pragma unroll
    for (int half = 0; half < 2; ++half) {
        int gr = r0 + half * 8;
        size_t base;
        int cs;
        if (mode == 0) {
            int e = gr / 3, i = gr - e * 3;
            base = (size_t)e * 576 + 64 + i;
            cs = 3;
        } else {
            int e = gr / 5, i = gr - e * 5;
            base = (size_t)e * 576 + 256 + i;
            cs = 5;
        }
#pragma unroll
        for (int nt = 0; nt < 8; ++nt) {
            int col = nt * 8 + tid * 2;
            out[base + (size_t)col * cs] = alpha * c[nt][half * 2];
            out[base + (size_t)(col + 1) * cs] = alpha * c[nt][half * 2 + 1];
        }
    }
}

extern "C" void kernel_launch(void* const* d_in, const int* in_sizes, int n_in,
                              void* d_out, int out_size) {
    const float* vectors = (const float*)d_in[0];
    const float* x       = (const float*)d_in[1];
    const float* V       = (const float*)d_in[2];
    const int*   senders = (const int*)d_in[3];
    const float* Ww      = (const float*)d_in[4];
    const float* W1      = (const float*)d_in[5];
    const float* W2      = (const float*)d_in[6];
    const float* W3      = (const float*)d_in[7];
    const float* Wl1     = (const float*)d_in[8];
    const float* Wl2     = (const float*)d_in[9];
    float* out = (float*)d_out;

    cudaFuncSetAttribute(mlp_kernel, cudaFuncAttributeMaxDynamicSharedMemorySize,
                         26112 * 4);
    cudaFuncSetAttribute(gemm_mma_kernel, cudaFuncAttributeMaxDynamicSharedMemorySize,
                         GM_SMEM);

    w3j_kernel<<<14, 128>>>();
    shc_kernel<<<1, 1>>>();
    zero_cnt_kernel<<<16, 256>>>();
    edge_pre_kernel<<<1024, 256>>>(vectors, x, Ww, senders);
    scan_kernel<<<1, 1024>>>();
    scatter_kernel<<<E_EDGES / 1024, 1024>>>(senders);
    node_accum_kernel<<<N_NODES, 256>>>();
    edge_main_kernel<<<E_EDGES / 4, 256>>>(V, senders);
    mlp_kernel<<<512, 256, 26112 * 4>>>(x, W1, W2, W3, out);
    gemm_mma_kernel<<<4096, 256, GM_SMEM>>>(Wl1, Wl2, out);
}

// round 14
// speedup vs baseline: 1.0020x; 1.0020x over previous
#include <cuda_runtime.h>
#include <cuda_bf16.h>
#include <math.h>
#include <stdint.h>

#define E_EDGES 65536
#define N_NODES 4096

// ---------------- device scratch ----------------
__device__ float g_w3j[678];
__device__ float g_shc[2];
__device__ float g_w[E_EDGES * 64];
__device__ float g_Y[E_EDGES * 16];
__device__ float g_len[E_EDGES];
__device__ int   g_cnt[N_NODES];
__device__ int   g_off[N_NODES + 1];
__device__ int   g_cursor[N_NODES];
__device__ int   g_sorted[E_EDGES];
__device__ float g_nodewY[N_NODES * 1024];
__device__ float g_S[E_EDGES * 192];
// bf16 hi/lo planes of the GEMM A matrices (row-major, K=320)
__device__ unsigned short g_A1h[E_EDGES * 3 * 320];
__device__ unsigned short g_A1l[E_EDGES * 3 * 320];
__device__ unsigned short g_A2h[E_EDGES * 5 * 320];
__device__ unsigned short g_A2l[E_EDGES * 5 * 320];

// ---------- f32x2 helpers ----------
__device__ __forceinline__ unsigned long long pack2(float x) {
    unsigned long long r;
    unsigned int xi = __float_as_uint(x);
    asm("mov.b64 %0, {%1, %1};" : "=l"(r) : "r"(xi));
    return r;
}
__device__ __forceinline__ float2 unpack2(unsigned long long v) {
    unsigned int lo, hi;
    asm("mov.b64 {%0, %1}, %2;" : "=r"(lo), "=r"(hi) : "l"(v));
    return make_float2(__uint_as_float(lo), __uint_as_float(hi));
}
#define FMA2(acc, a, b) \
    asm("fma.rn.f32x2 %0, %1, %2, %0;" : "+l"(acc) : "l"(a), "l"(b))

// ---------- bf16 helpers ----------
__device__ __forceinline__ unsigned short f2bf(float v) {
    __nv_bfloat16 b = __float2bfloat16(v);
    return *reinterpret_cast<unsigned short*>(&b);
}
__device__ __forceinline__ float bf2f(unsigned short s) {
    __nv_bfloat16 b = *reinterpret_cast<__nv_bfloat16*>(&s);
    return __bfloat162float(b);
}

// ---------- classic tensor-core mma (base ISA, works on sm_103) ----------
__device__ __forceinline__ void mma16816(float* c, const uint32_t* a, uint32_t b0, uint32_t b1) {
    asm volatile(
        "mma.sync.aligned.m16n8k16.row.col.f32.bf16.bf16.f32 "
        "{%0,%1,%2,%3}, {%4,%5,%6,%7}, {%8,%9}, {%0,%1,%2,%3};"
        : "+f"(c[0]), "+f"(c[1]), "+f"(c[2]), "+f"(c[3])
        : "r"(a[0]), "r"(a[1]), "r"(a[2]), "r"(a[3]), "r"(b0), "r"(b1));
}

__device__ double dfact(int n) {
    double r = 1.0;
    for (int i = 2; i <= n; ++i) r *= (double)i;
    return r;
}

__device__ double su2_cg(int j1, int j2, int j3, int m1, int m2, int m3) {
    if (m3 != m1 + m2) return 0.0;
    double pref = sqrt((2.0 * j3 + 1.0) * dfact(j3 + j1 - j2) * dfact(j3 - j1 + j2) *
                       dfact(j1 + j2 - j3) / dfact(j1 + j2 + j3 + 1));
    pref *= sqrt(dfact(j3 + m3) * dfact(j3 - m3) * dfact(j1 - m1) * dfact(j1 + m1) *
                 dfact(j2 - m2) * dfact(j2 + m2));
    double s = 0.0;
    for (int k = 0; k <= j1 + j2 - j3; ++k) {
        int d0 = k, d1 = j1 + j2 - j3 - k, d2 = j1 - m1 - k, d3 = j2 + m2 - k;
        int d4 = j3 - j2 + m1 + k, d5 = j3 - j1 - m2 + k;
        if (d0 < 0 || d1 < 0 || d2 < 0 || d3 < 0 || d4 < 0 || d5 < 0) continue;
        double den = dfact(d0) * dfact(d1) * dfact(d2) * dfact(d3) * dfact(d4) * dfact(d5);
        s += ((k & 1) ? -1.0 : 1.0) / den;
    }
    return pref * s;
}

__device__ void build_q(int l, double* qr, double* qi) {
    for (int i = 0; i < 49; ++i) { qr[i] = 0.0; qi[i] = 0.0; }
    const double is2 = 0.70710678118654752440;
    for (int m = -l; m < 0; ++m) {
        qr[(l + m) * 7 + (l - m)] = is2;
        qi[(l + m) * 7 + (l + m)] = -is2;
    }
    qr[l * 7 + l] = 1.0;
    for (int m = 1; m <= l; ++m) {
        double sg = (m & 1) ? -1.0 : 1.0;
        qr[(l + m) * 7 + (l + m)] = sg * is2;
        qi[(l + m) * 7 + (l - m)] = sg * is2;
    }
    int lm = l & 3;
    double pr, pi;
    if (lm == 0) { pr = 1; pi = 0; }
    else if (lm == 1) { pr = 0; pi = -1; }
    else if (lm == 2) { pr = -1; pi = 0; }
    else { pr = 0; pi = 1; }
    for (int i = 0; i < 49; ++i) {
        double r = qr[i], im = qi[i];
        qr[i] = pr * r - pi * im;
        qi[i] = pr * im + pi * r;
    }
}

__global__ void w3j_kernel() {
    const int L1[14] = {0, 1, 2, 0, 1, 1, 2, 3, 0, 1, 2, 2, 3, 2};
    const int L2[14] = {0, 1, 2, 1, 0, 2, 1, 2, 2, 1, 0, 2, 1, 1};
    const int L3[14] = {0, 0, 0, 1, 1, 1, 1, 1, 2, 2, 2, 2, 2, 3};
    const int OFFS[14] = {0, 1, 10, 35, 44, 53, 98, 143, 248, 273, 318, 343, 468, 573};
    int p = blockIdx.x;
    int t = threadIdx.x;
    int l1 = L1[p], l2 = L2[p], l3 = L3[p];
    int n1 = 2 * l1 + 1, n2 = 2 * l2 + 1, n3 = 2 * l3 + 1;
    int ntot = n1 * n2 * n3;

    __shared__ double sC[125];
    __shared__ double q1r[49], q1i[49], q2r[49], q2i[49], q3r[49], q3i[49];
    __shared__ double red[128];

    if (t < ntot) {
        int a = t / (n2 * n3);
        int b = (t / n3) % n2;
        int c = t % n3;
        sC[t] = su2_cg(l1, l2, l3, a - l1, b - l2, c - l3);
    }
    if (t == 0) {
        build_q(l1, q1r, q1i);
        build_q(l2, q2r, q2i);
        build_q(l3, q3r, q3i);
    }
    __syncthreads();

    double cr = 0.0;
    if (t < ntot) {
        int i = t / (n2 * n3);
        int j = (t / n3) % n2;
        int k = t % n3;
        for (int a = 0; a < n1; ++a) {
            double ar = q1r[a * 7 + i], ai = q1i[a * 7 + i];
            for (int b = 0; b < n2; ++b) {
                double br = q2r[b * 7 + j], bi = q2i[b * 7 + j];
                double tr = ar * br - ai * bi;
                double ti = ar * bi + ai * br;
                for (int c = 0; c < n3; ++c) {
                    double c3r = q3r[c * 7 + k], c3i = q3i[c * 7 + k];
                    double re = tr * c3r + ti * c3i;
                    cr += re * sC[(a * n2 + b) * n3 + c];
                }
            }
        }
    }
    red[t] = (t < ntot) ? cr * cr : 0.0;
    __syncthreads();
    for (int s = 64; s > 0; s >>= 1) {
        if (t < s) red[t] += red[t + s];
        __syncthreads();
    }
    double inv = 1.0 / sqrt(red[0]);
    if (t < ntot) g_w3j[OFFS[p] + t] = (float)(cr * inv);
}

__global__ void shc_kernel() {
    double u0[3] = {0.3, -0.4, sqrt(0.75)};
    double y1[3];
    for (int i = 0; i < 3; ++i) y1[i] = sqrt(3.0) * u0[i];
    double y2r[5] = {0, 0, 0, 0, 0};
    for (int i = 0; i < 3; ++i)
        for (int j = 0; j < 3; ++j)
            for (int k = 0; k < 5; ++k)
                y2r[k] += y1[i] * y1[j] * (double)g_w3j[273 + (i * 3 + j) * 5 + k];
    double n2s = 0;
    for (int k = 0; k < 5; ++k) n2s += y2r[k] * y2r[k];
    double c2 = sqrt(5.0) / sqrt(n2s);
    double y3r[7] = {0, 0, 0, 0, 0, 0, 0};
    for (int i = 0; i < 5; ++i)
        for (int j = 0; j < 3; ++j)
            for (int k = 0; k < 7; ++k)
                y3r[k] += (c2 * y2r[i]) * y1[j] * (double)g_w3j[573 + (i * 3 + j) * 7 + k];
    double n3s = 0;
    for (int k = 0; k < 7; ++k) n3s += y3r[k] * y3r[k];
    double c3 = sqrt(7.0) / sqrt(n3s);
    g_shc[0] = (float)c2;
    g_shc[1] = (float)c3;
}

__global__ void zero_cnt_kernel() {
    int i = blockIdx.x * blockDim.x + threadIdx.x;
    if (i < N_NODES) g_cnt[i] = 0;
}

// ------------- edge pre -------------
__global__ __launch_bounds__(256) void edge_pre_kernel(
    const float* __restrict__ vectors, const float* __restrict__ x,
    const float* __restrict__ Ww, const int* __restrict__ senders) {
    __shared__ float sWwT[4096];
    __shared__ float shx[1024];
    int t = threadIdx.x;
    int slot = t >> 6, u = t & 63;
    for (int i = t; i < 4096; i += 256) {
        int f4 = i >> 8, uu = (i >> 2) & 63, fr = i & 3;
        sWwT[i] = Ww[(f4 * 4 + fr) * 64 + uu];
    }
    __syncthreads();

    for (int it = 0; it < 16; ++it) {
        int e = blockIdx.x * 64 + it * 4 + slot;
        shx[slot * 256 + u] = x[e * 64 + u];
        __syncthreads();
        unsigned long long acc01 = 0ull, acc23 = 0ull;
        const ulonglong2* xp = (const ulonglong2*)(shx + slot * 256);
#pragma unroll
        for (int f4 = 0; f4 < 16; ++f4) {
            ulonglong2 xv = xp[f4];
            ulonglong2 wv = *(const ulonglong2*)(sWwT + f4 * 256 + u * 4);
            FMA2(acc01, xv.x, wv.x);
            FMA2(acc23, xv.y, wv.y);
        }
        float2 p01 = unpack2(acc01);
        float2 p23 = unpack2(acc23);
        float acc = (p01.x + p01.y) + (p23.x + p23.y);
        g_w[e * 64 + u] = acc * 0.125f;

        if (u < 16) {
            float vx = vectors[e * 3 + 0], vy = vectors[e * 3 + 1], vz = vectors[e * 3 + 2];
            float len = sqrtf(vx * vx + vy * vy + vz * vz);
            float inv = 1.0f / (len + 1e-12f);
            float y1[3] = {1.7320508075688772f * vx * inv,
                           1.7320508075688772f * vy * inv,
                           1.7320508075688772f * vz * inv};
            float C2 = g_shc[0], C3 = g_shc[1];
            float y2[5] = {0, 0, 0, 0, 0};
#pragma unroll
            for (int i = 0; i < 3; ++i)
#pragma unroll
                for (int j = 0; j < 3; ++j) {
                    float ab = y1[i] * y1[j];
#pragma unroll
                    for (int k = 0; k < 5; ++k) y2[k] += ab * g_w3j[273 + (i * 3 + j) * 5 + k];
                }
#pragma unroll
            for (int k = 0; k < 5; ++k) y2[k] *= C2;
            float Yv;
            if (u == 0) Yv = 1.0f;
            else if (u < 4) Yv = y1[u - 1];
            else if (u < 9) Yv = y2[u - 4];
            else {
                int k = u - 9;
                float s = 0.f;
#pragma unroll
                for (int i = 0; i < 5; ++i)
#pragma unroll
                    for (int j = 0; j < 3; ++j)
                        s += y2[i] * y1[j] * g_w3j[573 + (i * 3 + j) * 7 + k];
                Yv = C3 * s;
            }
            g_Y[e * 16 + u] = Yv;
            if (u == 0) {
                g_len[e] = len;
                atomicAdd(&g_cnt[senders[e]], 1);
            }
        }
        __syncthreads();
    }
}

// ------------- scan -------------
__global__ void scan_kernel() {
    int t = threadIdx.x;
    int b = t * 4;
    int v0 = g_cnt[b], v1 = g_cnt[b + 1], v2 = g_cnt[b + 2], v3 = g_cnt[b + 3];
    int tsum = v0 + v1 + v2 + v3;
    int xv = tsum;
#pragma unroll
    for (int o = 1; o < 32; o <<= 1) {
        int y = __shfl_up_sync(0xffffffffu, xv, o);
        if ((t & 31) >= o) xv += y;
    }
    __shared__ int wsum[32];
    if ((t & 31) == 31) wsum[t >> 5] = xv;
    __syncthreads();
    if (t < 32) {
        int z = wsum[t];
#pragma unroll
        for (int o = 1; o < 32; o <<= 1) {
            int y = __shfl_up_sync(0xffffffffu, z, o);
            if (t >= o) z += y;
        }
        wsum[t] = z;
    }
    __syncthreads();
    int excl = xv - tsum + ((t >= 32) ? wsum[(t >> 5) - 1] : 0);
    int run = excl;
    g_off[b] = run; g_cursor[b] = run; run += v0;
    g_off[b + 1] = run; g_cursor[b + 1] = run; run += v1;
    g_off[b + 2] = run; g_cursor[b + 2] = run; run += v2;
    g_off[b + 3] = run; g_cursor[b + 3] = run; run += v3;
    if (t == 1023) g_off[N_NODES] = run;
}

__global__ void scatter_kernel(const int* __restrict__ senders) {
    int e = blockIdx.x * blockDim.x + threadIdx.x;
    int pos = atomicAdd(&g_cursor[senders[e]], 1);
    g_sorted[pos] = e;
}

// ------------- node accumulate -------------
__global__ __launch_bounds__(256) void node_accum_kernel() {
    int n = blockIdx.x, t = threadIdx.x;
    int s = g_off[n];
    int cnt = g_off[n + 1] - s;
    int uu = t >> 4, ii = t & 15;
    __shared__ float sw[64];
    __shared__ float sy[16];
    float a0 = 0, a1 = 0, a2 = 0, a3 = 0;
    for (int q = 0; q < cnt; ++q) {
        int e = g_sorted[s + q];
        __syncthreads();
        if (t < 64) sw[t] = g_w[e * 64 + t];
        else if (t < 80) sy[t - 64] = g_Y[e * 16 + (t - 64)];
        __syncthreads();
        float yv = sy[ii];
        a0 += sw[uu] * yv;
        a1 += sw[uu + 16] * yv;
        a2 += sw[uu + 32] * yv;
        a3 += sw[uu + 48] * yv;
    }
    float* dst = &g_nodewY[n * 1024];
    dst[uu * 16 + ii] = 0.25f * a0;
    dst[(uu + 16) * 16 + ii] = 0.25f * a1;
    dst[(uu + 32) * 16 + ii] = 0.25f * a2;
    dst[(uu + 48) * 16 + ii] = 0.25f * a3;
}

// ------------- main edge kernel: TP paths -> S, bf16 hi/lo A planes -------------
__global__ __launch_bounds__(256) void edge_main_kernel(
    const float* __restrict__ V, const int* __restrict__ senders) {
    __shared__ float sw3j[678];
    int t = threadIdx.x;
    for (int i = t; i < 678; i += 256) sw3j[i] = g_w3j[i];
    int slot = t >> 6, u = t & 63;
    int e = blockIdx.x * 4 + slot;
    int n = senders[e];
    __syncthreads();

    float wy[16];
    {
        const float4* wp = (const float4*)&g_nodewY[n * 1024 + u * 16];
        float4 q0 = wp[0], q1 = wp[1], q2 = wp[2], q3 = wp[3];
        wy[0] = q0.x; wy[1] = q0.y; wy[2] = q0.z; wy[3] = q0.w;
        wy[4] = q1.x; wy[5] = q1.y; wy[6] = q1.z; wy[7] = q1.w;
        wy[8] = q2.x; wy[9] = q2.y; wy[10] = q2.z; wy[11] = q2.w;
        wy[12] = q3.x; wy[13] = q3.y; wy[14] = q3.z; wy[15] = q3.w;
    }
    const float* Vr = V + (size_t)e * 576;
    float v0 = Vr[u];
    float v1[3], v2[5];
#pragma unroll
    for (int j = 0; j < 3; ++j) v1[j] = Vr[64 + u * 3 + j];
#pragma unroll
    for (int j = 0; j < 5; ++j) v2[j] = Vr[256 + u * 5 + j];

    // scalar paths
    float s0 = wy[0] * v0 * sw3j[0];
    float s1 = 0.f;
#pragma unroll
    for (int i = 0; i < 3; ++i)
#pragma unroll
        for (int j = 0; j < 3; ++j) s1 += wy[1 + i] * v1[j] * sw3j[1 + i * 3 + j];
    float s2 = 0.f;
#pragma unroll
    for (int i = 0; i < 5; ++i)
#pragma unroll
        for (int j = 0; j < 5; ++j) s2 += wy[4 + i] * v2[j] * sw3j[10 + i * 5 + j];
    g_S[e * 192 + u] = s0;
    g_S[e * 192 + 64 + u] = s1;
    g_S[e * 192 + 128 + u] = s2;

    // l3=1 paths
    float p[5][3];
#pragma unroll
    for (int pa = 0; pa < 5; ++pa)
#pragma unroll
        for (int k = 0; k < 3; ++k) p[pa][k] = 0.f;
#pragma unroll
    for (int j = 0; j < 3; ++j) {
        float ab = wy[0] * v1[j];
#pragma unroll
        for (int k = 0; k < 3; ++k) p[0][k] += ab * sw3j[35 + j * 3 + k];
    }
#pragma unroll
    for (int i = 0; i < 3; ++i) {
        float ab = wy[1 + i] * v0;
#pragma unroll
        for (int k = 0; k < 3; ++k) p[1][k] += ab * sw3j[44 + i * 3 + k];
    }
#pragma unroll
    for (int i = 0; i < 3; ++i)
#pragma unroll
        for (int j = 0; j < 5; ++j) {
            float ab = wy[1 + i] * v2[j];
#pragma unroll
            for (int k = 0; k < 3; ++k) p[2][k] += ab * sw3j[53 + (i * 5 + j) * 3 + k];
        }
#pragma unroll
    for (int i = 0; i < 5; ++i)
#pragma unroll
        for (int j = 0; j < 3; ++j) {
            float ab = wy[4 + i] * v1[j];
#pragma unroll
            for (int k = 0; k < 3; ++k) p[3][k] += ab * sw3j[98 + (i * 3 + j) * 3 + k];
        }
#pragma unroll
    for (int i = 0; i < 7; ++i)
#pragma unroll
        for (int j = 0; j < 5; ++j) {
            float ab = wy[9 + i] * v2[j];
#pragma unroll
            for (int k = 0; k < 3; ++k) p[4][k] += ab * sw3j[143 + (i * 5 + j) * 3 + k];
        }

    // l3=2 paths
    float dd[5][5];
#pragma unroll
    for (int pa = 0; pa < 5; ++pa)
#pragma unroll
        for (int k = 0; k < 5; ++k) dd[pa][k] = 0.f;
#pragma unroll
    for (int j = 0; j < 5; ++j) {
        float ab = wy[0] * v2[j];
#pragma unroll
        for (int k = 0; k < 5; ++k) dd[0][k] += ab * sw3j[248 + j * 5 + k];
    }
#pragma unroll
    for (int i = 0; i < 3; ++i)
#pragma unroll
        for (int j = 0; j < 3; ++j) {
            float ab = wy[1 + i] * v1[j];
#pragma unroll
            for (int k = 0; k < 5; ++k) dd[1][k] += ab * sw3j[273 + (i * 3 + j) * 5 + k];
        }
#pragma unroll
    for (int i = 0; i < 5; ++i) {
        float ab = wy[4 + i] * v0;
#pragma unroll
        for (int k = 0; k < 5; ++k) dd[2][k] += ab * sw3j[318 + i * 5 + k];
    }
#pragma unroll
    for (int i = 0; i < 5; ++i)
#pragma unroll
        for (int j = 0; j < 5; ++j) {
            float ab = wy[4 + i] * v2[j];
#pragma unroll
            for (int k = 0; k < 5; ++k) dd[3][k] += ab * sw3j[343 + (i * 5 + j) * 5 + k];
        }
#pragma unroll
    for (int i = 0; i < 7; ++i)
#pragma unroll
        for (int j = 0; j < 3; ++j) {
            float ab = wy[9 + i] * v1[j];
#pragma unroll
            for (int k = 0; k < 5; ++k) dd[4][k] += ab * sw3j[468 + (i * 3 + j) * 5 + k];
        }

    const float SQ3 = 1.7320508075688772f;
    const float SQ5 = 2.2360679774997896f;
#pragma unroll
    for (int k = 0; k < 3; ++k) {
        size_t rb = ((size_t)e * 3 + k) * 320;
#pragma unroll
        for (int pa = 0; pa < 5; ++pa) {
            float val = SQ3 * p[pa][k];
            unsigned short h = f2bf(val);
            g_A1h[rb + pa * 64 + u] = h;
            g_A1l[rb + pa * 64 + u] = f2bf(val - bf2f(h));
        }
    }
#pragma unroll
    for (int k = 0; k < 5; ++k) {
        size_t rb = ((size_t)e * 5 + k) * 320;
#pragma unroll
        for (int pa = 0; pa < 5; ++pa) {
            float val = SQ5 * dd[pa][k];
            unsigned short h = f2bf(val);
            g_A2h[rb + pa * 64 + u] = h;
            g_A2l[rb + pa * 64 + u] = f2bf(val - bf2f(h));
        }
    }
}

// ------------- fused 3-layer MLP + envelope -> out[:, 0:64] (f32x2) -------------
__global__ __launch_bounds__(256) void mlp_kernel(
    const float* __restrict__ x, const float* __restrict__ W1,
    const float* __restrict__ W2, const float* __restrict__ W3,
    float* __restrict__ out) {
    extern __shared__ float smemf[];
    float* sW1T = smemf;
    float* sW2T = smemf + 16384;
    float* sW3T = smemf + 20480;
    float* shh = smemf + 24576;
    float* sh1 = smemf + 25600;
    float* sh2 = smemf + 25856;
    int t = threadIdx.x;
    for (int i = t; i < 16384; i += 256) {
        int f4 = i >> 8, uu = (i >> 2) & 63, fr = i & 3;
        sW1T[i] = W1[(f4 * 4 + fr) * 64 + uu];
    }
    for (int i = t; i < 4096; i += 256) {
        int f4 = i >> 8, uu = (i >> 2) & 63, fr = i & 3;
        sW2T[i] = W2[(f4 * 4 + fr) * 64 + uu];
        sW3T[i] = W3[(f4 * 4 + fr) * 64 + uu];
    }
    __syncthreads();

    int s = t >> 6, u = t & 63;
    for (int it = 0; it < 32; ++it) {
        int ebase = blockIdx.x * 128 + it * 4;
        for (int l = 0; l < 4; ++l) {
            int f = t + l * 256;
            int es = ebase + (f >> 8);
            int idx = f & 255;
            shh[f] = (idx < 64) ? x[es * 64 + idx] : g_S[es * 192 + idx - 64];
        }
        __syncthreads();
        int e = ebase + s;
        unsigned long long a01 = 0ull, a23 = 0ull;
        const ulonglong2* xp = (const ulonglong2*)(shh + s * 256);
#pragma unroll
        for (int f4 = 0; f4 < 64; ++f4) {
            ulonglong2 xv = xp[f4];
            ulonglong2 wv = *(const ulonglong2*)(sW1T + f4 * 256 + u * 4);
            FMA2(a01, xv.x, wv.x);
            FMA2(a23, xv.y, wv.y);
        }
        float2 p01 = unpack2(a01), p23 = unpack2(a23);
        float a1 = ((p01.x + p01.y) + (p23.x + p23.y)) * 0.0625f;
        float h1 = a1 / (1.f + expf(-a1));
        sh1[s * 64 + u] = h1;
        __syncthreads();
        a01 = 0ull; a23 = 0ull;
        const ulonglong2* hp = (const ulonglong2*)(sh1 + s * 64);
#pragma unroll
        for (int f4 = 0; f4 < 16; ++f4) {
            ulonglong2 xv = hp[f4];
            ulonglong2 wv = *(const ulonglong2*)(sW2T + f4 * 256 + u * 4);
            FMA2(a01, xv.x, wv.x);
            FMA2(a23, xv.y, wv.y);
        }
        p01 = unpack2(a01); p23 = unpack2(a23);
        float a2 = ((p01.x + p01.y) + (p23.x + p23.y)) * 0.125f;
        float h2 = a2 / (1.f + expf(-a2));
        sh2[s * 64 + u] = h2;
        __syncthreads();
        a01 = 0ull; a23 = 0ull;
        const ulonglong2* hp2 = (const ulonglong2*)(sh2 + s * 64);
#pragma unroll
        for (int f4 = 0; f4 < 16; ++f4) {
            ulonglong2 xv = hp2[f4];
            ulonglong2 wv = *(const ulonglong2*)(sW3T + f4 * 256 + u * 4);
            FMA2(a01, xv.x, wv.x);
            FMA2(a23, xv.y, wv.y);
        }
        p01 = unpack2(a01); p23 = unpack2(a23);
        float a3 = ((p01.x + p01.y) + (p23.x + p23.y)) * 0.125f;
        float d = g_len[e];
        float d3 = d * d * d;
        float d6 = d3 * d3, d7 = d6 * d, d8 = d7 * d;
        float env = (d < 1.0f) ? (1.0f - 28.0f * d6 + 48.0f * d7 - 21.0f * d8) : 0.0f;
        out[(size_t)e * 576 + u] = env * a3;
        __syncthreads();
    }
}

// ------------- mma.sync bf16-split GEMM -------------
// Block: 8 warps, 128 rows; warp w -> rows [w*16, w*16+16). N=64 (8 n8-tiles).
// B (Wl) hi/lo in smem col-major [n][k], stride 328 bf16 (conflict-free).
// A fragments loaded directly from global bf16 planes.
// blocks [0,1536): A1 (mode 0); [1536,4096): A2 (mode 1).
#define BSTR 328
#define GM_SMEM (2 * 64 * BSTR * 2)   // 83968 bytes

__global__ __launch_bounds__(256) void gemm_mma_kernel(
    const float* __restrict__ Wl1, const float* __restrict__ Wl2,
    float* __restrict__ out) {
    extern __shared__ unsigned short sB[];
    unsigned short* sBh = sB;
    unsigned short* sBl = sB + 64 * BSTR;

    int t = threadIdx.x;
    int w = t >> 5, lane = t & 31;
    int gid = lane >> 2, tid = lane & 3;

    int mode, row0;
    const float* Wl;
    const unsigned short *Ah, *Al;
    if (blockIdx.x < 1536) {
        mode = 0; row0 = blockIdx.x * 128;
        Wl = Wl1; Ah = g_A1h; Al = g_A1l;
    } else {
        mode = 1; row0 = (blockIdx.x - 1536) * 128;
        Wl = Wl2; Ah = g_A2h; Al = g_A2l;
    }

    // Fill B smem: col-major [n][k], hi/lo split. Wl is [v=320][n=64] row-major.
    for (int i = t; i < 320 * 64; i += 256) {
        int v = i >> 6, n = i & 63;
        float f = Wl[i];
        unsigned short h = f2bf(f);
        sBh[n * BSTR + v] = h;
        sBl[n * BSTR + v] = f2bf(f - bf2f(h));
    }
    __syncthreads();

    // accumulators: 8 n-tiles x 4 f32
    float c[8][4];
#pragma unroll
    for (int nt = 0; nt < 8; ++nt)
#pragma unroll
        for (int j = 0; j < 4; ++j) c[nt][j] = 0.f;

    int r0 = row0 + w * 16 + gid;      // row for a0/a2 (c0,c1)
    const unsigned short* ahp = Ah + (size_t)r0 * 320 + tid * 2;
    const unsigned short* alp = Al + (size_t)r0 * 320 + tid * 2;

    for (int kc = 0; kc < 20; ++kc) {
        int ko = kc * 16;
        uint32_t ah[4], al[4];
        ah[0] = *(const uint32_t*)(ahp + ko);
        ah[1] = *(const uint32_t*)(ahp + 8 * 320 + ko);
        ah[2] = *(const uint32_t*)(ahp + ko + 8);
        ah[3] = *(const uint32_t*)(ahp + 8 * 320 + ko + 8);
        al[0] = *(const uint32_t*)(alp + ko);
        al[1] = *(const uint32_t*)(alp + 8 * 320 + ko);
        al[2] = *(const uint32_t*)(alp + ko + 8);
        al[3] = *(const uint32_t*)(alp + 8 * 320 + ko + 8);
#pragma unroll
        for (int nt = 0; nt < 8; ++nt) {
            const unsigned short* bh = sBh + (nt * 8 + gid) * BSTR + ko + tid * 2;
            const unsigned short* bl = sBl + (nt * 8 + gid) * BSTR + ko + tid * 2;
            uint32_t bh0 = *(const uint32_t*)(bh);
            uint32_t bh1 = *(const uint32_t*)(bh + 8);
            uint32_t bl0 = *(const uint32_t*)(bl);
            uint32_t bl1 = *(const uint32_t*)(bl + 8);
            mma16816(c[nt], ah, bh0, bh1);
            mma16816(c[nt], ah, bl0, bl1);
            mma16816(c[nt], al, bh0, bh1);
        }
    }

    const float alpha = 0.05590169943749474f;  // 1/sqrt(320)
    // D layout: c0 = D[gid][tid*2], c1 = D[gid][tid*2+1],
    //           c2 = D[gid+8][tid*2], c3 = D[gid+8][tid*2+1]
#pragma unroll
    for (int half = 0; half < 2; ++half) {
        int gr = r0 + half * 8;
        size_t base;
        int cs;
        if (mode == 0) {
            int e = gr / 3, i = gr - e * 3;
            base = (size_t)e * 576 + 64 + i;
            cs = 3;
        } else {
            int e = gr / 5, i = gr - e * 5;
            base = (size_t)e * 576 + 256 + i;
            cs = 5;
        }
#pragma unroll
        for (int nt = 0; nt < 8; ++nt) {
            int col = nt * 8 + tid * 2;
            out[base + (size_t)col * cs] = alpha * c[nt][half * 2];
            out[base + (size_t)(col + 1) * cs] = alpha * c[nt][half * 2 + 1];
        }
    }
}

extern "C" void kernel_launch(void* const* d_in, const int* in_sizes, int n_in,
                              void* d_out, int out_size) {
    const float* vectors = (const float*)d_in[0];
    const float* x       = (const float*)d_in[1];
    const float* V       = (const float*)d_in[2];
    const int*   senders = (const int*)d_in[3];
    const float* Ww      = (const float*)d_in[4];
    const float* W1      = (const float*)d_in[5];
    const float* W2      = (const float*)d_in[6];
    const float* W3      = (const float*)d_in[7];
    const float* Wl1     = (const float*)d_in[8];
    const float* Wl2     = (const float*)d_in[9];
    float* out = (float*)d_out;

    cudaFuncSetAttribute(mlp_kernel, cudaFuncAttributeMaxDynamicSharedMemorySize,
                         26112 * 4);
    cudaFuncSetAttribute(gemm_mma_kernel, cudaFuncAttributeMaxDynamicSharedMemorySize,
                         GM_SMEM);

    w3j_kernel<<<14, 128>>>();
    shc_kernel<<<1, 1>>>();
    zero_cnt_kernel<<<16, 256>>>();
    edge_pre_kernel<<<1024, 256>>>(vectors, x, Ww, senders);
    scan_kernel<<<1, 1024>>>();
    scatter_kernel<<<E_EDGES / 1024, 1024>>>(senders);
    node_accum_kernel<<<N_NODES, 256>>>();
    edge_main_kernel<<<E_EDGES / 4, 256>>>(V, senders);
    mlp_kernel<<<512, 256, 26112 * 4>>>(x, W1, W2, W3, out);
    gemm_mma_kernel<<<4096, 256, GM_SMEM>>>(Wl1, Wl2, out);
}